// round 4
// baseline (speedup 1.0000x reference)
#include <cuda_runtime.h>
#include <math.h>

#define B_  2
#define S_  2048
#define D_  1024
#define H_  16
#define HD_ 64
#define M_  (B_*S_)   // 4096

// Scratch (device globals: allocation-free rule)
__device__ float g_q[B_*H_*S_*HD_];
__device__ float g_k[B_*H_*S_*HD_];
__device__ float g_v[B_*H_*S_*HD_];
__device__ float g_ctx[(size_t)M_*D_];

// ---------------------------------------------------------------------------
// QKV projection: y = x @ W^T + b, scattered to [B,H,S,HD]. blockIdx.z picks.
// 64x64 tile, BK=16, 256 threads, 4x4 per thread (strided i*16 mapping).
// ---------------------------------------------------------------------------
__global__ __launch_bounds__(256) void proj_kernel(
    const float* __restrict__ x,
    const float* __restrict__ Wq, const float* __restrict__ bq,
    const float* __restrict__ Wk, const float* __restrict__ bk,
    const float* __restrict__ Wv, const float* __restrict__ bv)
{
    const float* W; const float* bias; float* out;
    if (blockIdx.z == 0)      { W = Wq; bias = bq; out = g_q; }
    else if (blockIdx.z == 1) { W = Wk; bias = bk; out = g_k; }
    else                      { W = Wv; bias = bv; out = g_v; }

    __shared__ float Xs[16][65];
    __shared__ float Ws[16][65];

    const int tid = threadIdx.x;
    const int tx = tid & 15, ty = tid >> 4;
    const int m0 = blockIdx.y * 64;
    const int n0 = blockIdx.x * 64;

    float acc[4][4] = {};

    const int kk = tid & 15;
    const int rr = tid >> 4;

    for (int k0 = 0; k0 < D_; k0 += 16) {
        #pragma unroll
        for (int p = 0; p < 4; p++) {
            Xs[kk][rr + p*16] = x[(size_t)(m0 + rr + p*16) * D_ + k0 + kk];
            Ws[kk][rr + p*16] = W[(size_t)(n0 + rr + p*16) * D_ + k0 + kk];
        }
        __syncthreads();
        #pragma unroll
        for (int kq = 0; kq < 16; kq++) {
            float a[4], b[4];
            #pragma unroll
            for (int i = 0; i < 4; i++) a[i] = Xs[kq][ty + 16*i];
            #pragma unroll
            for (int j = 0; j < 4; j++) b[j] = Ws[kq][tx + 16*j];
            #pragma unroll
            for (int i = 0; i < 4; i++)
                #pragma unroll
                for (int j = 0; j < 4; j++)
                    acc[i][j] = fmaf(a[i], b[j], acc[i][j]);
        }
        __syncthreads();
    }

    #pragma unroll
    for (int i = 0; i < 4; i++) {
        const int m  = m0 + ty + 16*i;
        const int bb = m >> 11;          // /S_
        const int s  = m & (S_ - 1);
        #pragma unroll
        for (int j = 0; j < 4; j++) {
            const int n  = n0 + tx + 16*j;
            const int h  = n >> 6;       // /HD_
            const int hd = n & 63;
            out[((size_t)((bb*H_ + h)*S_ + s))*HD_ + hd] = acc[i][j] + bias[n];
        }
    }
}

// ---------------------------------------------------------------------------
// Output projection: out = ctx @ Wo^T + bo, plain [M,D] output.
// ---------------------------------------------------------------------------
__global__ __launch_bounds__(256) void oproj_kernel(
    const float* __restrict__ Wo, const float* __restrict__ bo,
    float* __restrict__ out)
{
    __shared__ float Xs[16][65];
    __shared__ float Ws[16][65];

    const int tid = threadIdx.x;
    const int tx = tid & 15, ty = tid >> 4;
    const int m0 = blockIdx.y * 64;
    const int n0 = blockIdx.x * 64;

    float acc[4][4] = {};

    const int kk = tid & 15;
    const int rr = tid >> 4;

    for (int k0 = 0; k0 < D_; k0 += 16) {
        #pragma unroll
        for (int p = 0; p < 4; p++) {
            Xs[kk][rr + p*16] = g_ctx[(size_t)(m0 + rr + p*16) * D_ + k0 + kk];
            Ws[kk][rr + p*16] = Wo[(size_t)(n0 + rr + p*16) * D_ + k0 + kk];
        }
        __syncthreads();
        #pragma unroll
        for (int kq = 0; kq < 16; kq++) {
            float a[4], b[4];
            #pragma unroll
            for (int i = 0; i < 4; i++) a[i] = Xs[kq][ty + 16*i];
            #pragma unroll
            for (int j = 0; j < 4; j++) b[j] = Ws[kq][tx + 16*j];
            #pragma unroll
            for (int i = 0; i < 4; i++)
                #pragma unroll
                for (int j = 0; j < 4; j++)
                    acc[i][j] = fmaf(a[i], b[j], acc[i][j]);
        }
        __syncthreads();
    }

    #pragma unroll
    for (int i = 0; i < 4; i++) {
        const int m = m0 + ty + 16*i;
        #pragma unroll
        for (int j = 0; j < 4; j++) {
            const int n = n0 + tx + 16*j;
            out[(size_t)m * D_ + n] = acc[i][j] + bo[n];
        }
    }
}

// ---------------------------------------------------------------------------
// Flash attention fp32. One CTA per (b*h, 64-row q tile). 256 threads.
// SMEM: Qs[d][s] / Ks[d][s] / Vs[s][d] / Ps[c][r], each 64x65 floats.
// ---------------------------------------------------------------------------
#define FLASH_SMEM (4 * 64 * 65 * (int)sizeof(float))

__global__ __launch_bounds__(256) void flash_kernel(const float* __restrict__ mask)
{
    extern __shared__ float sh[];
    float* Qs = sh;                 // [64][65]  (d-major: Qs[d*65+s])
    float* Ks = sh + 64*65;         // [64][65]  (d-major)
    float* Vs = sh + 2*64*65;       // [64][65]  (s-major: Vs[s*65+d])
    float* Ps = sh + 3*64*65;       // [64][65]  (c-major: Ps[c*65+r])

    const int tid = threadIdx.x;
    const int tx = tid & 15, ty = tid >> 4;
    const int bh = blockIdx.y;
    const int bb = bh >> 4;         // /H_
    const int h  = bh & 15;
    const int s0 = blockIdx.x * 64;
    const float scale = 0.125f;     // HD^-0.5

    const float* qp = g_q + ((size_t)bh * S_ + s0) * HD_;
    const float* kp = g_k + (size_t)bh * S_ * HD_;
    const float* vp = g_v + (size_t)bh * S_ * HD_;

    // Load Q tile transposed: Qs[d][s_local]
    #pragma unroll
    for (int p = 0; p < 16; p++) {
        int idx  = p*256 + tid;
        int srow = idx >> 6, d = idx & 63;
        Qs[d*65 + srow] = qp[(size_t)srow*HD_ + d];
    }

    float mstat[4], lstat[4], o[4][4];
    #pragma unroll
    for (int i = 0; i < 4; i++) {
        mstat[i] = -INFINITY; lstat[i] = 0.f;
        #pragma unroll
        for (int j = 0; j < 4; j++) o[i][j] = 0.f;
    }
    __syncthreads();

    for (int kt = 0; kt < S_/64; kt++) {
        const int k0 = kt * 64;

        // Load K (transposed) and V (direct)
        #pragma unroll
        for (int p = 0; p < 16; p++) {
            int idx  = p*256 + tid;
            int srow = idx >> 6, d = idx & 63;
            float kvv = kp[(size_t)(k0 + srow)*HD_ + d];
            float vvv = vp[(size_t)(k0 + srow)*HD_ + d];
            Ks[d*65 + srow]   = kvv;
            Vs[srow*65 + d]   = vvv;
        }
        __syncthreads();

        // S-tile = Q K^T
        float acc[4][4] = {};
        #pragma unroll
        for (int d = 0; d < 64; d++) {
            float a[4], b[4];
            #pragma unroll
            for (int i = 0; i < 4; i++) a[i] = Qs[d*65 + ty + 16*i];
            #pragma unroll
            for (int j = 0; j < 4; j++) b[j] = Ks[d*65 + tx + 16*j];
            #pragma unroll
            for (int i = 0; i < 4; i++)
                #pragma unroll
                for (int j = 0; j < 4; j++)
                    acc[i][j] = fmaf(a[i], b[j], acc[i][j]);
        }

        // Scale + mask
        #pragma unroll
        for (int i = 0; i < 4; i++) {
            const int qrow = s0 + ty + 16*i;
            const float* mrow = mask + ((size_t)bb * S_ + qrow) * S_ + k0;
            #pragma unroll
            for (int j = 0; j < 4; j++)
                acc[i][j] = acc[i][j] * scale + mrow[tx + 16*j];
        }

        // Online softmax update + write P^T to SMEM
        #pragma unroll
        for (int i = 0; i < 4; i++) {
            float rmax = acc[i][0];
            #pragma unroll
            for (int j = 1; j < 4; j++) rmax = fmaxf(rmax, acc[i][j]);
            #pragma unroll
            for (int off = 8; off > 0; off >>= 1)
                rmax = fmaxf(rmax, __shfl_xor_sync(0xffffffffu, rmax, off));

            const float mn  = fmaxf(mstat[i], rmax);
            const float fac = __expf(mstat[i] - mn);
            float rsum = 0.f;
            #pragma unroll
            for (int j = 0; j < 4; j++) {
                float pv = __expf(acc[i][j] - mn);
                Ps[(tx + 16*j)*65 + ty + 16*i] = pv;
                rsum += pv;
            }
            #pragma unroll
            for (int off = 8; off > 0; off >>= 1)
                rsum += __shfl_xor_sync(0xffffffffu, rsum, off);

            lstat[i] = lstat[i] * fac + rsum;
            mstat[i] = mn;
            #pragma unroll
            for (int j = 0; j < 4; j++) o[i][j] *= fac;
        }
        __syncthreads();

        // O += P @ V
        #pragma unroll
        for (int kd = 0; kd < 64; kd++) {
            float a[4], b[4];
            #pragma unroll
            for (int i = 0; i < 4; i++) a[i] = Ps[kd*65 + ty + 16*i];
            #pragma unroll
            for (int j = 0; j < 4; j++) b[j] = Vs[kd*65 + tx + 16*j];
            #pragma unroll
            for (int i = 0; i < 4; i++)
                #pragma unroll
                for (int j = 0; j < 4; j++)
                    o[i][j] = fmaf(a[i], b[j], o[i][j]);
        }
        __syncthreads();   // protect Ks/Vs/Ps before next tile load
    }

    // Final normalize + write ctx [B,S,D]
    #pragma unroll
    for (int i = 0; i < 4; i++) {
        const float inv = 1.f / lstat[i];
        const int srow = s0 + ty + 16*i;
        #pragma unroll
        for (int j = 0; j < 4; j++)
            g_ctx[((size_t)bb * S_ + srow) * D_ + h*HD_ + tx + 16*j] = o[i][j] * inv;
    }
}

// ---------------------------------------------------------------------------
extern "C" void kernel_launch(void* const* d_in, const int* in_sizes, int n_in,
                              void* d_out, int out_size)
{
    (void)in_sizes; (void)n_in; (void)out_size;
    const float* x    = (const float*)d_in[0];
    const float* mask = (const float*)d_in[1];
    const float* Wq   = (const float*)d_in[2];
    const float* bq   = (const float*)d_in[3];
    const float* Wk   = (const float*)d_in[4];
    const float* bk   = (const float*)d_in[5];
    const float* Wv   = (const float*)d_in[6];
    const float* bv   = (const float*)d_in[7];
    const float* Wo   = (const float*)d_in[8];
    const float* bo   = (const float*)d_in[9];
    float* out = (float*)d_out;

    // QKV projections (z = q/k/v)
    proj_kernel<<<dim3(D_/64, M_/64, 3), 256>>>(x, Wq, bq, Wk, bk, Wv, bv);

    // Flash attention
    cudaFuncSetAttribute(flash_kernel,
                         cudaFuncAttributeMaxDynamicSharedMemorySize, FLASH_SMEM);
    flash_kernel<<<dim3(S_/64, B_*H_), 256, FLASH_SMEM>>>(mask);

    // Output projection
    oproj_kernel<<<dim3(D_/64, M_/64), 256>>>(Wo, bo, out);
}

// round 6
// speedup vs baseline: 1.3852x; 1.3852x over previous
#include <cuda_runtime.h>
#include <math.h>

typedef unsigned long long ull;

#define B_  2
#define S_  2048
#define D_  1024
#define H_  16
#define HD_ 64
#define M_  (B_*S_)   // 4096

// Scratch (device globals: allocation-free rule)
__device__ float g_q[B_*H_*S_*HD_];
__device__ float g_k[B_*H_*S_*HD_];
__device__ float g_v[B_*H_*S_*HD_];
__device__ float g_ctx[(size_t)M_*D_];

// ---------------------------------------------------------------------------
// Packed f32x2 helpers (FFMA2 path — ptxas won't emit it from plain C++)
// ---------------------------------------------------------------------------
__device__ __forceinline__ ull dup2(float v) {
    ull r; asm("mov.b64 %0, {%1, %1};" : "=l"(r) : "f"(v)); return r;
}
__device__ __forceinline__ void fma2(ull& d, ull a, ull b) {
    asm("fma.rn.f32x2 %0, %1, %2, %0;" : "+l"(d) : "l"(a), "l"(b));
}
__device__ __forceinline__ void mul2(ull& d, ull a) {
    asm("mul.rn.f32x2 %0, %0, %1;" : "+l"(d) : "l"(a));
}
__device__ __forceinline__ float2 unp2(ull v) {
    float lo, hi; asm("mov.b64 {%0, %1}, %2;" : "=f"(lo), "=f"(hi) : "l"(v));
    return make_float2(lo, hi);
}

// ---------------------------------------------------------------------------
// GEMM mainloop: C[128x128] tile of  Y = X @ W^T  (X:[M,D], W:[N,D] row-major)
// 256 threads, 8x8 per thread via f32x2 pairs, double-buffered SMEM, BK=16.
// acc[i][p]: rows {my+i | i<4} and {my+64+i-4 | i>=4}, col pairs
// p=0:(nx,nx+1) p=1:(nx+2,nx+3) p=2:(nx+64,nx+65) p=3:(nx+66,nx+67).
// ---------------------------------------------------------------------------
#define BK   16
#define LDA  132   // 128 + 4 pad

__device__ __forceinline__ void stage_sts(float* __restrict__ Sm, int t,
                                          float4 v0, float4 v1) {
    const int r = t >> 2, c = (t & 3) * 4;
    Sm[(c+0)*LDA + r]      = v0.x;
    Sm[(c+1)*LDA + r]      = v0.y;
    Sm[(c+2)*LDA + r]      = v0.z;
    Sm[(c+3)*LDA + r]      = v0.w;
    Sm[(c+0)*LDA + r + 64] = v1.x;
    Sm[(c+1)*LDA + r + 64] = v1.y;
    Sm[(c+2)*LDA + r + 64] = v1.z;
    Sm[(c+3)*LDA + r + 64] = v1.w;
}

__device__ __forceinline__ void gemm_mainloop(
    const float* __restrict__ X, const float* __restrict__ W,
    int m0, int n0, float* __restrict__ As, float* __restrict__ Bs,
    ull acc[8][4])
{
    const int t  = threadIdx.x;
    const int lr = t >> 2, lc = (t & 3) * 4;
    const int my = (t >> 4) * 4;
    const int nx = (t & 15) * 4;

    const float* xp = X + (size_t)(m0 + lr) * D_ + lc;
    const float* wp = W + (size_t)(n0 + lr) * D_ + lc;

    // prologue: tile 0
    float4 xa0 = *(const float4*)(xp);
    float4 xa1 = *(const float4*)(xp + (size_t)64 * D_);
    float4 wb0 = *(const float4*)(wp);
    float4 wb1 = *(const float4*)(wp + (size_t)64 * D_);
    stage_sts(As, t, xa0, xa1);
    stage_sts(Bs, t, wb0, wb1);
    __syncthreads();

    const int NT = D_ / BK;   // 64
    for (int kt = 0; kt < NT; kt++) {
        if (kt < NT - 1) {
            const int k1 = (kt + 1) * BK;
            xa0 = *(const float4*)(xp + k1);
            xa1 = *(const float4*)(xp + (size_t)64 * D_ + k1);
            wb0 = *(const float4*)(wp + k1);
            wb1 = *(const float4*)(wp + (size_t)64 * D_ + k1);
        }
        const float* Asb = As + (kt & 1) * (BK * LDA);
        const float* Bsb = Bs + (kt & 1) * (BK * LDA);

        #pragma unroll
        for (int k = 0; k < BK; k++) {
            const float4 a0 = *(const float4*)(Asb + k*LDA + my);
            const float4 a1 = *(const float4*)(Asb + k*LDA + my + 64);
            const ulonglong2 b0 = *(const ulonglong2*)(Bsb + k*LDA + nx);
            const ulonglong2 b1 = *(const ulonglong2*)(Bsb + k*LDA + nx + 64);
            ull ad;
            ad = dup2(a0.x); fma2(acc[0][0],ad,b0.x); fma2(acc[0][1],ad,b0.y); fma2(acc[0][2],ad,b1.x); fma2(acc[0][3],ad,b1.y);
            ad = dup2(a0.y); fma2(acc[1][0],ad,b0.x); fma2(acc[1][1],ad,b0.y); fma2(acc[1][2],ad,b1.x); fma2(acc[1][3],ad,b1.y);
            ad = dup2(a0.z); fma2(acc[2][0],ad,b0.x); fma2(acc[2][1],ad,b0.y); fma2(acc[2][2],ad,b1.x); fma2(acc[2][3],ad,b1.y);
            ad = dup2(a0.w); fma2(acc[3][0],ad,b0.x); fma2(acc[3][1],ad,b0.y); fma2(acc[3][2],ad,b1.x); fma2(acc[3][3],ad,b1.y);
            ad = dup2(a1.x); fma2(acc[4][0],ad,b0.x); fma2(acc[4][1],ad,b0.y); fma2(acc[4][2],ad,b1.x); fma2(acc[4][3],ad,b1.y);
            ad = dup2(a1.y); fma2(acc[5][0],ad,b0.x); fma2(acc[5][1],ad,b0.y); fma2(acc[5][2],ad,b1.x); fma2(acc[5][3],ad,b1.y);
            ad = dup2(a1.z); fma2(acc[6][0],ad,b0.x); fma2(acc[6][1],ad,b0.y); fma2(acc[6][2],ad,b1.x); fma2(acc[6][3],ad,b1.y);
            ad = dup2(a1.w); fma2(acc[7][0],ad,b0.x); fma2(acc[7][1],ad,b0.y); fma2(acc[7][2],ad,b1.x); fma2(acc[7][3],ad,b1.y);
        }
        if (kt < NT - 1) {
            float* Asn = As + ((kt + 1) & 1) * (BK * LDA);
            float* Bsn = Bs + ((kt + 1) & 1) * (BK * LDA);
            stage_sts(Asn, t, xa0, xa1);
            stage_sts(Bsn, t, wb0, wb1);
        }
        __syncthreads();
    }
}

// ---------------------------------------------------------------------------
// QKV projection: y = x @ W^T + b, scattered to [B,H,S,HD]. blockIdx.z picks.
// ---------------------------------------------------------------------------
__global__ __launch_bounds__(256, 2) void proj_kernel(
    const float* __restrict__ x,
    const float* __restrict__ Wq, const float* __restrict__ bq,
    const float* __restrict__ Wk, const float* __restrict__ bk,
    const float* __restrict__ Wv, const float* __restrict__ bv)
{
    const float* W; const float* bias; float* out;
    if (blockIdx.z == 0)      { W = Wq; bias = bq; out = g_q; }
    else if (blockIdx.z == 1) { W = Wk; bias = bk; out = g_k; }
    else                      { W = Wv; bias = bv; out = g_v; }

    __shared__ float As[2 * BK * LDA];
    __shared__ float Bs[2 * BK * LDA];

    const int m0 = blockIdx.y * 128;
    const int n0 = blockIdx.x * 128;

    ull acc[8][4] = {};
    gemm_mainloop(x, W, m0, n0, As, Bs, acc);

    const int t  = threadIdx.x;
    const int my = (t >> 4) * 4;
    const int nx = (t & 15) * 4;

    const float4 bi0 = *(const float4*)(bias + n0 + nx);
    const float4 bi1 = *(const float4*)(bias + n0 + nx + 64);

    #pragma unroll
    for (int r = 0; r < 8; r++) {
        const int m  = m0 + my + (r & 3) + (r >> 2) * 64;
        const int bb = m >> 11;
        const int s  = m & (S_ - 1);
        // col block 0
        {
            const int n = n0 + nx;
            const float2 c0 = unp2(acc[r][0]), c1 = unp2(acc[r][1]);
            float4 v = make_float4(c0.x + bi0.x, c0.y + bi0.y,
                                   c1.x + bi0.z, c1.y + bi0.w);
            *(float4*)&out[(((size_t)bb * H_ + (n >> 6)) * S_ + s) * HD_ + (n & 63)] = v;
        }
        // col block 1
        {
            const int n = n0 + nx + 64;
            const float2 c0 = unp2(acc[r][2]), c1 = unp2(acc[r][3]);
            float4 v = make_float4(c0.x + bi1.x, c0.y + bi1.y,
                                   c1.x + bi1.z, c1.y + bi1.w);
            *(float4*)&out[(((size_t)bb * H_ + (n >> 6)) * S_ + s) * HD_ + (n & 63)] = v;
        }
    }
}

// ---------------------------------------------------------------------------
// Output projection: out = ctx @ Wo^T + bo, plain [M,D] output.
// ---------------------------------------------------------------------------
__global__ __launch_bounds__(256, 2) void oproj_kernel(
    const float* __restrict__ Wo, const float* __restrict__ bo,
    float* __restrict__ out)
{
    __shared__ float As[2 * BK * LDA];
    __shared__ float Bs[2 * BK * LDA];

    const int m0 = blockIdx.y * 128;
    const int n0 = blockIdx.x * 128;

    ull acc[8][4] = {};
    gemm_mainloop(g_ctx, Wo, m0, n0, As, Bs, acc);

    const int t  = threadIdx.x;
    const int my = (t >> 4) * 4;
    const int nx = (t & 15) * 4;

    const float4 bi0 = *(const float4*)(bo + n0 + nx);
    const float4 bi1 = *(const float4*)(bo + n0 + nx + 64);

    #pragma unroll
    for (int r = 0; r < 8; r++) {
        const int m = m0 + my + (r & 3) + (r >> 2) * 64;
        {
            const float2 c0 = unp2(acc[r][0]), c1 = unp2(acc[r][1]);
            float4 v = make_float4(c0.x + bi0.x, c0.y + bi0.y,
                                   c1.x + bi0.z, c1.y + bi0.w);
            *(float4*)&out[(size_t)m * D_ + n0 + nx] = v;
        }
        {
            const float2 c0 = unp2(acc[r][2]), c1 = unp2(acc[r][3]);
            float4 v = make_float4(c0.x + bi1.x, c0.y + bi1.y,
                                   c1.x + bi1.z, c1.y + bi1.w);
            *(float4*)&out[(size_t)m * D_ + n0 + nx + 64] = v;
        }
    }
}

// ---------------------------------------------------------------------------
// Flash attention fp32, f32x2 packed math. One CTA per (b*h, 64-row q tile).
// 256 threads as 16x16; thread fragment = rows [4ty,4ty+4), cols [4tx,4tx+4).
// Qs/Ks: d-major [64][FPAD]; Vs: s-major [64][FPAD]; Ps: col-major [64][FPAD].
// ---------------------------------------------------------------------------
#define FPAD 68
#define FLASH_SMEM (4 * 64 * FPAD * (int)sizeof(float))

__global__ __launch_bounds__(256, 2) void flash_kernel(const float* __restrict__ mask)
{
    extern __shared__ float sh[];
    float* Qs = sh;
    float* Ks = sh + 64 * FPAD;
    float* Vs = sh + 2 * 64 * FPAD;
    float* Ps = sh + 3 * 64 * FPAD;

    const int tid = threadIdx.x;
    const int tx = tid & 15, ty = tid >> 4;
    const int my = ty * 4, nx = tx * 4;
    const int bh = blockIdx.y;
    const int bb = bh >> 4;
    const int h  = bh & 15;
    const int s0 = blockIdx.x * 64;
    const float scale = 0.125f;

    const float* qp = g_q + ((size_t)bh * S_ + s0) * HD_;
    const float* kp = g_k + (size_t)bh * S_ * HD_;
    const float* vp = g_v + (size_t)bh * S_ * HD_;

    // stage Q transposed (d-major) via register transpose, conflict-free STS.128
    {
        const int sb = (tid & 15) * 4, d4 = (tid >> 4) * 4;
        const float4 r0 = *(const float4*)(qp + (size_t)(sb + 0) * HD_ + d4);
        const float4 r1 = *(const float4*)(qp + (size_t)(sb + 1) * HD_ + d4);
        const float4 r2 = *(const float4*)(qp + (size_t)(sb + 2) * HD_ + d4);
        const float4 r3 = *(const float4*)(qp + (size_t)(sb + 3) * HD_ + d4);
        *(float4*)&Qs[(d4 + 0) * FPAD + sb] = make_float4(r0.x, r1.x, r2.x, r3.x);
        *(float4*)&Qs[(d4 + 1) * FPAD + sb] = make_float4(r0.y, r1.y, r2.y, r3.y);
        *(float4*)&Qs[(d4 + 2) * FPAD + sb] = make_float4(r0.z, r1.z, r2.z, r3.z);
        *(float4*)&Qs[(d4 + 3) * FPAD + sb] = make_float4(r0.w, r1.w, r2.w, r3.w);
    }

    float mstat[4], lstat[4];
    ull o[4][2];
    #pragma unroll
    for (int i = 0; i < 4; i++) {
        mstat[i] = -INFINITY; lstat[i] = 0.f;
        o[i][0] = 0ull; o[i][1] = 0ull;
    }
    __syncthreads();

    for (int kt = 0; kt < S_ / 64; kt++) {
        const int k0 = kt * 64;

        // stage K transposed + V direct
        {
            const int sb = (tid & 15) * 4, d4 = (tid >> 4) * 4;
            const float* kpp = kp + (size_t)k0 * HD_;
            const float4 r0 = *(const float4*)(kpp + (size_t)(sb + 0) * HD_ + d4);
            const float4 r1 = *(const float4*)(kpp + (size_t)(sb + 1) * HD_ + d4);
            const float4 r2 = *(const float4*)(kpp + (size_t)(sb + 2) * HD_ + d4);
            const float4 r3 = *(const float4*)(kpp + (size_t)(sb + 3) * HD_ + d4);
            *(float4*)&Ks[(d4 + 0) * FPAD + sb] = make_float4(r0.x, r1.x, r2.x, r3.x);
            *(float4*)&Ks[(d4 + 1) * FPAD + sb] = make_float4(r0.y, r1.y, r2.y, r3.y);
            *(float4*)&Ks[(d4 + 2) * FPAD + sb] = make_float4(r0.z, r1.z, r2.z, r3.z);
            *(float4*)&Ks[(d4 + 3) * FPAD + sb] = make_float4(r0.w, r1.w, r2.w, r3.w);
            #pragma unroll
            for (int p = 0; p < 4; p++) {
                const int c = tid + 256 * p;
                const int sr = c >> 4, dc = (c & 15) * 4;
                *(float4*)&Vs[sr * FPAD + dc] =
                    *(const float4*)(vp + (size_t)(k0 + sr) * HD_ + dc);
            }
        }
        __syncthreads();

        // S-tile = Q K^T (packed)
        ull acc[4][2] = {};
        #pragma unroll 16
        for (int d = 0; d < 64; d++) {
            const float4 a = *(const float4*)&Qs[d * FPAD + my];
            const ulonglong2 b = *(const ulonglong2*)&Ks[d * FPAD + nx];
            ull ad;
            ad = dup2(a.x); fma2(acc[0][0], ad, b.x); fma2(acc[0][1], ad, b.y);
            ad = dup2(a.y); fma2(acc[1][0], ad, b.x); fma2(acc[1][1], ad, b.y);
            ad = dup2(a.z); fma2(acc[2][0], ad, b.x); fma2(acc[2][1], ad, b.y);
            ad = dup2(a.w); fma2(acc[3][0], ad, b.x); fma2(acc[3][1], ad, b.y);
        }

        // scale + mask + online softmax, write P^T
        #pragma unroll
        for (int i = 0; i < 4; i++) {
            const int qrow = s0 + my + i;
            const float4 mr =
                *(const float4*)(mask + ((size_t)bb * S_ + qrow) * S_ + k0 + nx);
            const float2 p0 = unp2(acc[i][0]);
            const float2 p1 = unp2(acc[i][1]);
            float sc[4];
            sc[0] = fmaf(p0.x, scale, mr.x);
            sc[1] = fmaf(p0.y, scale, mr.y);
            sc[2] = fmaf(p1.x, scale, mr.z);
            sc[3] = fmaf(p1.y, scale, mr.w);

            float rmax = fmaxf(fmaxf(sc[0], sc[1]), fmaxf(sc[2], sc[3]));
            #pragma unroll
            for (int off = 8; off > 0; off >>= 1)
                rmax = fmaxf(rmax, __shfl_xor_sync(0xffffffffu, rmax, off));

            const float mn  = fmaxf(mstat[i], rmax);
            const float fac = __expf(mstat[i] - mn);
            float rsum = 0.f;
            #pragma unroll
            for (int j = 0; j < 4; j++) {
                const float pv = __expf(sc[j] - mn);
                Ps[(nx + j) * FPAD + my + i] = pv;
                rsum += pv;
            }
            #pragma unroll
            for (int off = 8; off > 0; off >>= 1)
                rsum += __shfl_xor_sync(0xffffffffu, rsum, off);

            lstat[i] = lstat[i] * fac + rsum;
            mstat[i] = mn;
            const ull fd = dup2(fac);
            mul2(o[i][0], fd);
            mul2(o[i][1], fd);
        }
        __syncthreads();

        // O += P @ V (packed)
        #pragma unroll 16
        for (int kd = 0; kd < 64; kd++) {
            const float4 a = *(const float4*)&Ps[kd * FPAD + my];
            const ulonglong2 b = *(const ulonglong2*)&Vs[kd * FPAD + nx];
            ull ad;
            ad = dup2(a.x); fma2(o[0][0], ad, b.x); fma2(o[0][1], ad, b.y);
            ad = dup2(a.y); fma2(o[1][0], ad, b.x); fma2(o[1][1], ad, b.y);
            ad = dup2(a.z); fma2(o[2][0], ad, b.x); fma2(o[2][1], ad, b.y);
            ad = dup2(a.w); fma2(o[3][0], ad, b.x); fma2(o[3][1], ad, b.y);
        }
        __syncthreads();
    }

    // normalize + write ctx [B,S,D]
    #pragma unroll
    for (int i = 0; i < 4; i++) {
        const float inv = 1.f / lstat[i];
        const float2 u0 = unp2(o[i][0]);
        const float2 u1 = unp2(o[i][1]);
        const float4 v = make_float4(u0.x * inv, u0.y * inv, u1.x * inv, u1.y * inv);
        *(float4*)&g_ctx[((size_t)bb * S_ + s0 + my + i) * D_ + h * HD_ + nx] = v;
    }
}

// ---------------------------------------------------------------------------
extern "C" void kernel_launch(void* const* d_in, const int* in_sizes, int n_in,
                              void* d_out, int out_size)
{
    (void)in_sizes; (void)n_in; (void)out_size;
    const float* x    = (const float*)d_in[0];
    const float* mask = (const float*)d_in[1];
    const float* Wq   = (const float*)d_in[2];
    const float* bq   = (const float*)d_in[3];
    const float* Wk   = (const float*)d_in[4];
    const float* bk   = (const float*)d_in[5];
    const float* Wv   = (const float*)d_in[6];
    const float* bv   = (const float*)d_in[7];
    const float* Wo   = (const float*)d_in[8];
    const float* bo   = (const float*)d_in[9];
    float* out = (float*)d_out;

    // QKV projections (z = q/k/v)
    proj_kernel<<<dim3(D_/128, M_/128, 3), 256>>>(x, Wq, bq, Wk, bk, Wv, bv);

    // Flash attention
    cudaFuncSetAttribute(flash_kernel,
                         cudaFuncAttributeMaxDynamicSharedMemorySize, FLASH_SMEM);
    flash_kernel<<<dim3(S_/64, B_*H_), 256, FLASH_SMEM>>>(mask);

    // Output projection
    oproj_kernel<<<dim3(D_/128, M_/128), 256>>>(Wo, bo, out);
}